// round 14
// baseline (speedup 1.0000x reference)
#include <cuda_runtime.h>

#define EPS 0.001f
#define TS 9   // table stride in floats (odd -> <=2-way LDS bank conflicts)
typedef unsigned long long u64;

// ---- packed f32x2 helpers (sm_100+) ----
__device__ __forceinline__ u64 pk2(float lo, float hi) {
    u64 r; asm("mov.b64 %0,{%1,%2};" : "=l"(r) : "f"(lo), "f"(hi)); return r;
}
__device__ __forceinline__ void upk2(u64 v, float& lo, float& hi) {
    asm("mov.b64 {%0,%1},%2;" : "=f"(lo), "=f"(hi) : "l"(v));
}
__device__ __forceinline__ u64 ffma2(u64 a, u64 b, u64 c) {
    u64 d; asm("fma.rn.f32x2 %0,%1,%2,%3;" : "=l"(d) : "l"(a), "l"(b), "l"(c)); return d;
}

struct W1p { u64 c0[3], c1[3], bp[3]; };  // W1 columns / b1, packed over j-pairs

// Per-mask table entry (9 floats):
//  [0..3] S00 S01 S10 S11  (pre-mask Jacobian of s3 wrt q)
//  [4..5] sb0 sb1          (s3 = S q + sb)
//  [6..7] E0 E1            (dlo_dq; lo = E q + lb)
//  [8]    lb

// Front end: z (packed over j-pairs), ReLU mask, g accumulation.
__device__ __forceinline__ void row_front(
    float q0, float q1, const W1p& w, const float* __restrict__ w2r,
    float gb0, float gb1, int& mask, float& g0, float& g1)
{
    const u64 q0p = pk2(q0, q0), q1p = pk2(q1, q1);
    float z[6];
    upk2(ffma2(w.c0[0], q0p, ffma2(w.c1[0], q1p, w.bp[0])), z[0], z[1]);
    upk2(ffma2(w.c0[1], q0p, ffma2(w.c1[1], q1p, w.bp[1])), z[2], z[3]);
    upk2(ffma2(w.c0[2], q0p, ffma2(w.c1[2], q1p, w.bp[2])), z[4], z[5]);

    unsigned nmask = 0;
    g0 = gb0; g1 = gb1;
#pragma unroll
    for (int j = 0; j < 6; j++) {
        nmask |= (__float_as_uint(z[j]) & 0x80000000u) >> (31 - j);
        float h = fmaxf(z[j], 0.0f);
        g0 = fmaf(w2r[j],     h, g0);
        g1 = fmaf(w2r[6 + j], h, g1);
    }
    mask = (int)(nmask ^ 0x3Fu);
}

// Scalar tail on pre-loaded table registers (R11-proven dataflow).
__device__ __forceinline__ void row_tail(
    float q0, float q1, float qd0, float qd1, float qdd0, float qdd1,
    const float ev[9], float g0, float g1, float& t0, float& t1)
{
    const float S00 = ev[0], S01 = ev[1], S10 = ev[2], S11 = ev[3];
    const float s30 = fmaf(S00, q0, fmaf(S01, q1, ev[4]));
    const float s31 = fmaf(S10, q0, fmaf(S11, q1, ev[5]));
    const float E0 = ev[6], E1 = ev[7];
    const float c = fmaf(E0, q0, fmaf(E1, q1, ev[8]));   // lo

    const float a = fmaxf(s30, 0.0f);
    const float b = fmaxf(s31, 0.0f);

    const float d00 = (s30 > 0.0f) ? S00 : 0.0f;
    const float d01 = (s30 > 0.0f) ? S01 : 0.0f;
    const float d10 = (s31 > 0.0f) ? S10 : 0.0f;
    const float d11 = (s31 > 0.0f) ? S11 : 0.0f;

    const float da = fmaf(d00, qd0, d01 * qd1);
    const float db = fmaf(d10, qd0, d11 * qd1);
    const float dc = fmaf(E0,  qd0, E1  * qd1);

    const float Lq0 = a * qdd0;
    const float Lq1 = fmaf(c, qdd0, b * qdd1);
    const float Hq0 = fmaf(a, Lq0, fmaf(c, Lq1, EPS * qdd0));
    const float Hq1 = fmaf(b, Lq1, EPS * qdd1);

    const float ada = a * da;
    const float dh01 = fmaf(a, dc, c * da);
    const float dHq0 = fmaf(ada + ada, qd0, dh01 * qd1);
    const float cdb = fmaf(c, dc, b * db);
    const float dHq1 = fmaf(dh01, qd0, (cdb + cdb) * qd1);

    const float Ltq0 = fmaf(a, qd0, c * qd1);
    const float Ltq1 = b * qd1;
    const float tw0 = Ltq0 + Ltq0;
    const float tw1 = Ltq1 + Ltq1;
    const float P0 = tw0 * qd0;
    const float P1 = tw0 * qd1;
    const float P2 = tw1 * qd1;

    const float base0 = Hq0 + dHq0 + g0;
    const float base1 = Hq1 + dHq1 + g1;
    t0 = fmaf(d00, P0, fmaf(E0, P1, fmaf(d10, P2, base0)));
    t1 = fmaf(d01, P0, fmaf(E1, P1, fmaf(d11, P2, base1)));
}

__global__ void __launch_bounds__(128, 7)
lnn_tau_kernel(const float* __restrict__ x,
               const float* __restrict__ W1, const float* __restrict__ b1,
               const float* __restrict__ W2, const float* __restrict__ b2,
               const float* __restrict__ W3, const float* __restrict__ b3,
               const float* __restrict__ W4, const float* __restrict__ b4,
               float* __restrict__ out, int n)
{
    __shared__ float tab[64 * TS];

    // Build the 64-entry mask table (S, sb, E, lb).
    if (threadIdx.x < 64) {
        const int m = threadIdx.x;
        float S00 = 0.f, S01 = 0.f, S10 = 0.f, S11 = 0.f;
        float sb0 = b3[0], sb1 = b3[1];
        float E0 = 0.f, E1 = 0.f, lb = b4[0];
#pragma unroll
        for (int j = 0; j < 6; j++) {
            if ((m >> j) & 1) {
                const float a0 = W1[2 * j], a1 = W1[2 * j + 1], bb = b1[j];
                const float w30 = W3[j], w31 = W3[6 + j], w4j = W4[j];
                S00 = fmaf(w30, a0, S00); S01 = fmaf(w30, a1, S01); sb0 = fmaf(w30, bb, sb0);
                S10 = fmaf(w31, a0, S10); S11 = fmaf(w31, a1, S11); sb1 = fmaf(w31, bb, sb1);
                E0  = fmaf(w4j, a0, E0);  E1  = fmaf(w4j, a1, E1);  lb  = fmaf(w4j, bb, lb);
            }
        }
        float* e = tab + m * TS;
        e[0] = S00; e[1] = S01; e[2] = S10; e[3] = S11;
        e[4] = sb0; e[5] = sb1;
        e[6] = E0;  e[7] = E1;  e[8] = lb;
    }

    // Per-thread weight registers, loaded ONCE, amortized over the grid-stride loop.
    W1p w;
#pragma unroll
    for (int p = 0; p < 3; p++) {
        w.c0[p] = pk2(__ldg(W1 + 4 * p),     __ldg(W1 + 4 * p + 2));
        w.c1[p] = pk2(__ldg(W1 + 4 * p + 1), __ldg(W1 + 4 * p + 3));
        w.bp[p] = pk2(__ldg(b1 + 2 * p),     __ldg(b1 + 2 * p + 1));
    }
    float w2r[12];
#pragma unroll
    for (int j = 0; j < 6; j++) {
        w2r[j]     = __ldg(W2 + j);
        w2r[6 + j] = __ldg(W2 + 6 + j);
    }
    const float gb0 = __ldg(b2 + 0);
    const float gb1 = __ldg(b2 + 1);
    __syncthreads();

    const int np = n >> 1;  // pairs of rows
    const int stride = gridDim.x * blockDim.x;

    for (int p = blockIdx.x * blockDim.x + threadIdx.x; p < np; p += stride) {
        const float4* xp = reinterpret_cast<const float4*>(x + (size_t)p * 12);
        const float4 u0 = xp[0], u1 = xp[1], u2 = xp[2];
        // rowA = (u0.x,u0.y | u0.z,u0.w | u1.x,u1.y)
        // rowB = (u1.z,u1.w | u2.x,u2.y | u2.z,u2.w)

        // 1) both fronts (masks + g)
        int maskA, maskB;
        float g0A, g1A, g0B, g1B;
        row_front(u0.x, u0.y, w, w2r, gb0, gb1, maskA, g0A, g1A);
        row_front(u1.z, u1.w, w, w2r, gb0, gb1, maskB, g0B, g1B);

        // 2) both table lookups issued back-to-back (18 LDS in flight)
        const float* eA = tab + maskA * TS;
        const float* eB = tab + maskB * TS;
        float evA[9], evB[9];
#pragma unroll
        for (int k = 0; k < 9; k++) evA[k] = eA[k];
#pragma unroll
        for (int k = 0; k < 9; k++) evB[k] = eB[k];

        // 3) both scalar tails
        float o0, o1, o2, o3;
        row_tail(u0.x, u0.y, u0.z, u0.w, u1.x, u1.y, evA, g0A, g1A, o0, o1);
        row_tail(u1.z, u1.w, u2.x, u2.y, u2.z, u2.w, evB, g0B, g1B, o2, o3);

        reinterpret_cast<float4*>(out)[p] = make_float4(o0, o1, o2, o3);
    }

    // Tail (n odd) — n is even here; kept for safety.
    if ((n & 1) && blockIdx.x == 0 && threadIdx.x == 0) {
        const int row = n - 1;
        const float* xr = x + (size_t)row * 6;
        int mask; float g0, g1;
        row_front(xr[0], xr[1], w, w2r, gb0, gb1, mask, g0, g1);
        float ev[9];
#pragma unroll
        for (int k = 0; k < 9; k++) ev[k] = tab[mask * TS + k];
        float t0, t1;
        row_tail(xr[0], xr[1], xr[2], xr[3], xr[4], xr[5], ev, g0, g1, t0, t1);
        out[(size_t)row * 2 + 0] = t0;
        out[(size_t)row * 2 + 1] = t1;
    }
}

extern "C" void kernel_launch(void* const* d_in, const int* in_sizes, int n_in,
                              void* d_out, int out_size)
{
    const float* x  = (const float*)d_in[0];
    const float* W1 = (const float*)d_in[1];
    const float* b1 = (const float*)d_in[2];
    const float* W2 = (const float*)d_in[3];
    const float* b2 = (const float*)d_in[4];
    const float* W3 = (const float*)d_in[5];
    const float* b3 = (const float*)d_in[6];
    const float* W4 = (const float*)d_in[7];
    const float* b4 = (const float*)d_in[8];
    float* out = (float*)d_out;

    const int n = in_sizes[0] / 6;   // rows

    // Persistent-style grid: 7 blocks/SM resident, grid-stride (~8 iters/thread)
    const int threads = 128;
    const int blocks = 148 * 7;
    lnn_tau_kernel<<<blocks, threads>>>(x, W1, b1, W2, b2, W3, b3, W4, b4, out, n);
}

// round 15
// speedup vs baseline: 1.3114x; 1.3114x over previous
#include <cuda_runtime.h>

#define EPS 0.001f
#define TS 9   // table stride in floats (odd -> <=2-way LDS bank conflicts)
typedef unsigned long long u64;

// ---- packed f32x2 helpers (sm_100+) ----
__device__ __forceinline__ u64 pk2(float lo, float hi) {
    u64 r; asm("mov.b64 %0,{%1,%2};" : "=l"(r) : "f"(lo), "f"(hi)); return r;
}
__device__ __forceinline__ void upk2(u64 v, float& lo, float& hi) {
    asm("mov.b64 {%0,%1},%2;" : "=f"(lo), "=f"(hi) : "l"(v));
}
__device__ __forceinline__ u64 ffma2(u64 a, u64 b, u64 c) {
    u64 d; asm("fma.rn.f32x2 %0,%1,%2,%3;" : "=l"(d) : "l"(a), "l"(b), "l"(c)); return d;
}

struct W1p { u64 c0[3], c1[3], bp[3]; };  // W1 columns / b1, packed over j-pairs

// Per-mask table entry (9 floats):
//  [0..3] S00 S01 S10 S11  (pre-mask Jacobian of s3 wrt q)
//  [4..5] sb0 sb1          (s3 = S q + sb)
//  [6..7] E0 E1            (dlo_dq; lo = E q + lb)
//  [8]    lb

// R11-proven per-row computation (packed z front, scalar tail).
__device__ __forceinline__ void compute_row(
    float q0, float q1, float qd0, float qd1, float qdd0, float qdd1,
    const W1p& w, const float* __restrict__ w2r, float gb0, float gb1,
    const float* __restrict__ tab, float& t0, float& t1)
{
    const u64 q0p = pk2(q0, q0), q1p = pk2(q1, q1);
    float z[6];
    upk2(ffma2(w.c0[0], q0p, ffma2(w.c1[0], q1p, w.bp[0])), z[0], z[1]);
    upk2(ffma2(w.c0[1], q0p, ffma2(w.c1[1], q1p, w.bp[1])), z[2], z[3]);
    upk2(ffma2(w.c0[2], q0p, ffma2(w.c1[2], q1p, w.bp[2])), z[4], z[5]);

    unsigned nmask = 0;
    float g0 = gb0, g1 = gb1;
#pragma unroll
    for (int j = 0; j < 6; j++) {
        nmask |= (__float_as_uint(z[j]) & 0x80000000u) >> (31 - j);
        float h = fmaxf(z[j], 0.0f);
        g0 = fmaf(w2r[j],     h, g0);
        g1 = fmaf(w2r[6 + j], h, g1);
    }
    const int mask = (int)(nmask ^ 0x3Fu);

    const float* e = tab + mask * TS;
    const float S00 = e[0], S01 = e[1], S10 = e[2], S11 = e[3];
    const float s30 = fmaf(S00, q0, fmaf(S01, q1, e[4]));
    const float s31 = fmaf(S10, q0, fmaf(S11, q1, e[5]));
    const float E0 = e[6], E1 = e[7];
    const float c = fmaf(E0, q0, fmaf(E1, q1, e[8]));   // lo

    const float a = fmaxf(s30, 0.0f);
    const float b = fmaxf(s31, 0.0f);

    const float d00 = (s30 > 0.0f) ? S00 : 0.0f;
    const float d01 = (s30 > 0.0f) ? S01 : 0.0f;
    const float d10 = (s31 > 0.0f) ? S10 : 0.0f;
    const float d11 = (s31 > 0.0f) ? S11 : 0.0f;

    const float da = fmaf(d00, qd0, d01 * qd1);
    const float db = fmaf(d10, qd0, d11 * qd1);
    const float dc = fmaf(E0,  qd0, E1  * qd1);

    const float Lq0 = a * qdd0;
    const float Lq1 = fmaf(c, qdd0, b * qdd1);
    const float Hq0 = fmaf(a, Lq0, fmaf(c, Lq1, EPS * qdd0));
    const float Hq1 = fmaf(b, Lq1, EPS * qdd1);

    const float ada = a * da;
    const float dh01 = fmaf(a, dc, c * da);
    const float dHq0 = fmaf(ada + ada, qd0, dh01 * qd1);
    const float cdb = fmaf(c, dc, b * db);
    const float dHq1 = fmaf(dh01, qd0, (cdb + cdb) * qd1);

    const float Ltq0 = fmaf(a, qd0, c * qd1);
    const float Ltq1 = b * qd1;
    const float tw0 = Ltq0 + Ltq0;
    const float tw1 = Ltq1 + Ltq1;
    const float P0 = tw0 * qd0;
    const float P1 = tw0 * qd1;
    const float P2 = tw1 * qd1;

    const float base0 = Hq0 + dHq0 + g0;
    const float base1 = Hq1 + dHq1 + g1;
    t0 = fmaf(d00, P0, fmaf(E0, P1, fmaf(d10, P2, base0)));
    t1 = fmaf(d01, P0, fmaf(E1, P1, fmaf(d11, P2, base1)));
}

__global__ void __launch_bounds__(128, 6)
lnn_tau_kernel(const float* __restrict__ x,
               const float* __restrict__ W1, const float* __restrict__ b1,
               const float* __restrict__ W2, const float* __restrict__ b2,
               const float* __restrict__ W3, const float* __restrict__ b3,
               const float* __restrict__ W4, const float* __restrict__ b4,
               float* __restrict__ out, int n)
{
    __shared__ float tab[64 * TS];

    // Build the 64-entry mask table (S, sb, E, lb).
    if (threadIdx.x < 64) {
        const int m = threadIdx.x;
        float S00 = 0.f, S01 = 0.f, S10 = 0.f, S11 = 0.f;
        float sb0 = b3[0], sb1 = b3[1];
        float E0 = 0.f, E1 = 0.f, lb = b4[0];
#pragma unroll
        for (int j = 0; j < 6; j++) {
            if ((m >> j) & 1) {
                const float a0 = W1[2 * j], a1 = W1[2 * j + 1], bb = b1[j];
                const float w30 = W3[j], w31 = W3[6 + j], w4j = W4[j];
                S00 = fmaf(w30, a0, S00); S01 = fmaf(w30, a1, S01); sb0 = fmaf(w30, bb, sb0);
                S10 = fmaf(w31, a0, S10); S11 = fmaf(w31, a1, S11); sb1 = fmaf(w31, bb, sb1);
                E0  = fmaf(w4j, a0, E0);  E1  = fmaf(w4j, a1, E1);  lb  = fmaf(w4j, bb, lb);
            }
        }
        float* e = tab + m * TS;
        e[0] = S00; e[1] = S01; e[2] = S10; e[3] = S11;
        e[4] = sb0; e[5] = sb1;
        e[6] = E0;  e[7] = E1;  e[8] = lb;
    }

    // Per-thread weight registers, loaded ONCE, amortized over the grid-stride loop.
    W1p w;
#pragma unroll
    for (int p = 0; p < 3; p++) {
        w.c0[p] = pk2(__ldg(W1 + 4 * p),     __ldg(W1 + 4 * p + 2));
        w.c1[p] = pk2(__ldg(W1 + 4 * p + 1), __ldg(W1 + 4 * p + 3));
        w.bp[p] = pk2(__ldg(b1 + 2 * p),     __ldg(b1 + 2 * p + 1));
    }
    float w2r[12];
#pragma unroll
    for (int j = 0; j < 6; j++) {
        w2r[j]     = __ldg(W2 + j);
        w2r[6 + j] = __ldg(W2 + 6 + j);
    }
    const float gb0 = __ldg(b2 + 0);
    const float gb1 = __ldg(b2 + 1);
    __syncthreads();

    const int np = n >> 1;  // pairs of rows
    const int stride = gridDim.x * blockDim.x;
    int p = blockIdx.x * blockDim.x + threadIdx.x;

    // 2 pairs per loop body: all 6 LDG.128 issued before either tail (MLP=6).
    for (; p + stride < np; p += 2 * stride) {
        const int p2 = p + stride;
        const float4* xa = reinterpret_cast<const float4*>(x + (size_t)p  * 12);
        const float4* xb = reinterpret_cast<const float4*>(x + (size_t)p2 * 12);
        const float4 a0 = xa[0], a1 = xa[1], a2 = xa[2];
        const float4 b0 = xb[0], b1v = xb[1], b2v = xb[2];

        float o0, o1, o2, o3;
        compute_row(a0.x, a0.y, a0.z, a0.w, a1.x, a1.y, w, w2r, gb0, gb1, tab, o0, o1);
        compute_row(a1.z, a1.w, a2.x, a2.y, a2.z, a2.w, w, w2r, gb0, gb1, tab, o2, o3);
        reinterpret_cast<float4*>(out)[p] = make_float4(o0, o1, o2, o3);

        float r0, r1, r2, r3;
        compute_row(b0.x, b0.y, b0.z, b0.w, b1v.x, b1v.y, w, w2r, gb0, gb1, tab, r0, r1);
        compute_row(b1v.z, b1v.w, b2v.x, b2v.y, b2v.z, b2v.w, w, w2r, gb0, gb1, tab, r2, r3);
        reinterpret_cast<float4*>(out)[p2] = make_float4(r0, r1, r2, r3);
    }

    // Remainder: at most one pair left for this thread.
    if (p < np) {
        const float4* xa = reinterpret_cast<const float4*>(x + (size_t)p * 12);
        const float4 a0 = xa[0], a1 = xa[1], a2 = xa[2];
        float o0, o1, o2, o3;
        compute_row(a0.x, a0.y, a0.z, a0.w, a1.x, a1.y, w, w2r, gb0, gb1, tab, o0, o1);
        compute_row(a1.z, a1.w, a2.x, a2.y, a2.z, a2.w, w, w2r, gb0, gb1, tab, o2, o3);
        reinterpret_cast<float4*>(out)[p] = make_float4(o0, o1, o2, o3);
    }

    // Tail (n odd) — n is even here; kept for safety.
    if ((n & 1) && blockIdx.x == 0 && threadIdx.x == 0) {
        const int row = n - 1;
        const float* xr = x + (size_t)row * 6;
        float t0, t1;
        compute_row(xr[0], xr[1], xr[2], xr[3], xr[4], xr[5],
                    w, w2r, gb0, gb1, tab, t0, t1);
        out[(size_t)row * 2 + 0] = t0;
        out[(size_t)row * 2 + 1] = t1;
    }
}

extern "C" void kernel_launch(void* const* d_in, const int* in_sizes, int n_in,
                              void* d_out, int out_size)
{
    const float* x  = (const float*)d_in[0];
    const float* W1 = (const float*)d_in[1];
    const float* b1 = (const float*)d_in[2];
    const float* W2 = (const float*)d_in[3];
    const float* b2 = (const float*)d_in[4];
    const float* W3 = (const float*)d_in[5];
    const float* b3 = (const float*)d_in[6];
    const float* W4 = (const float*)d_in[7];
    const float* b4 = (const float*)d_in[8];
    float* out = (float*)d_out;

    const int n = in_sizes[0] / 6;   // rows

    // Persistent-style grid: 6 blocks/SM resident, grid-stride (~4 double-iters/thread)
    const int threads = 128;
    const int blocks = 148 * 6;
    lnn_tau_kernel<<<blocks, threads>>>(x, W1, b1, W2, b2, W3, b3, W4, b4, out, n);
}

// round 16
// speedup vs baseline: 1.3341x; 1.0172x over previous
#include <cuda_runtime.h>

#define EPS 0.001f
#define TS 9   // table stride in floats (odd -> <=2-way LDS bank conflicts)
typedef unsigned long long u64;

// ---- packed f32x2 helpers (sm_100+) ----
__device__ __forceinline__ u64 pk2(float lo, float hi) {
    u64 r; asm("mov.b64 %0,{%1,%2};" : "=l"(r) : "f"(lo), "f"(hi)); return r;
}
__device__ __forceinline__ void upk2(u64 v, float& lo, float& hi) {
    asm("mov.b64 {%0,%1},%2;" : "=f"(lo), "=f"(hi) : "l"(v));
}
__device__ __forceinline__ u64 ffma2(u64 a, u64 b, u64 c) {
    u64 d; asm("fma.rn.f32x2 %0,%1,%2,%3;" : "=l"(d) : "l"(a), "l"(b), "l"(c)); return d;
}

struct W1p { u64 c0[3], c1[3], bp[3]; };  // W1 columns / b1, packed over j-pairs

// Per-mask table entry (9 floats):
//  [0..3] S00 S01 S10 S11  (pre-mask Jacobian of s3 wrt q)
//  [4..5] sb0 sb1          (s3 = S q + sb)
//  [6..7] E0 E1            (dlo_dq; lo = E q + lb)
//  [8]    lb

// R11-proven per-row computation (packed z front, scalar tail).
__device__ __forceinline__ void compute_row(
    float q0, float q1, float qd0, float qd1, float qdd0, float qdd1,
    const W1p& w, const float* __restrict__ w2r, float gb0, float gb1,
    const float* __restrict__ tab, float& t0, float& t1)
{
    const u64 q0p = pk2(q0, q0), q1p = pk2(q1, q1);
    float z[6];
    upk2(ffma2(w.c0[0], q0p, ffma2(w.c1[0], q1p, w.bp[0])), z[0], z[1]);
    upk2(ffma2(w.c0[1], q0p, ffma2(w.c1[1], q1p, w.bp[1])), z[2], z[3]);
    upk2(ffma2(w.c0[2], q0p, ffma2(w.c1[2], q1p, w.bp[2])), z[4], z[5]);

    unsigned nmask = 0;
    float g0 = gb0, g1 = gb1;
#pragma unroll
    for (int j = 0; j < 6; j++) {
        nmask |= (__float_as_uint(z[j]) & 0x80000000u) >> (31 - j);
        float h = fmaxf(z[j], 0.0f);
        g0 = fmaf(w2r[j],     h, g0);
        g1 = fmaf(w2r[6 + j], h, g1);
    }
    const int mask = (int)(nmask ^ 0x3Fu);

    const float* e = tab + mask * TS;
    const float S00 = e[0], S01 = e[1], S10 = e[2], S11 = e[3];
    const float s30 = fmaf(S00, q0, fmaf(S01, q1, e[4]));
    const float s31 = fmaf(S10, q0, fmaf(S11, q1, e[5]));
    const float E0 = e[6], E1 = e[7];
    const float c = fmaf(E0, q0, fmaf(E1, q1, e[8]));   // lo

    const float a = fmaxf(s30, 0.0f);
    const float b = fmaxf(s31, 0.0f);

    const float d00 = (s30 > 0.0f) ? S00 : 0.0f;
    const float d01 = (s30 > 0.0f) ? S01 : 0.0f;
    const float d10 = (s31 > 0.0f) ? S10 : 0.0f;
    const float d11 = (s31 > 0.0f) ? S11 : 0.0f;

    const float da = fmaf(d00, qd0, d01 * qd1);
    const float db = fmaf(d10, qd0, d11 * qd1);
    const float dc = fmaf(E0,  qd0, E1  * qd1);

    const float Lq0 = a * qdd0;
    const float Lq1 = fmaf(c, qdd0, b * qdd1);
    const float Hq0 = fmaf(a, Lq0, fmaf(c, Lq1, EPS * qdd0));
    const float Hq1 = fmaf(b, Lq1, EPS * qdd1);

    const float ada = a * da;
    const float dh01 = fmaf(a, dc, c * da);
    const float dHq0 = fmaf(ada + ada, qd0, dh01 * qd1);
    const float cdb = fmaf(c, dc, b * db);
    const float dHq1 = fmaf(dh01, qd0, (cdb + cdb) * qd1);

    const float Ltq0 = fmaf(a, qd0, c * qd1);
    const float Ltq1 = b * qd1;
    const float tw0 = Ltq0 + Ltq0;
    const float tw1 = Ltq1 + Ltq1;
    const float P0 = tw0 * qd0;
    const float P1 = tw0 * qd1;
    const float P2 = tw1 * qd1;

    const float base0 = Hq0 + dHq0 + g0;
    const float base1 = Hq1 + dHq1 + g1;
    t0 = fmaf(d00, P0, fmaf(E0, P1, fmaf(d10, P2, base0)));
    t1 = fmaf(d01, P0, fmaf(E1, P1, fmaf(d11, P2, base1)));
}

__device__ __forceinline__ void do_pair(
    const float4& v0, const float4& v1, const float4& v2,
    const W1p& w, const float* __restrict__ w2r, float gb0, float gb1,
    const float* __restrict__ tab, float4& o)
{
    float o0, o1, o2, o3;
    compute_row(v0.x, v0.y, v0.z, v0.w, v1.x, v1.y, w, w2r, gb0, gb1, tab, o0, o1);
    compute_row(v1.z, v1.w, v2.x, v2.y, v2.z, v2.w, w, w2r, gb0, gb1, tab, o2, o3);
    o = make_float4(o0, o1, o2, o3);
}

__global__ void __launch_bounds__(128, 5)
lnn_tau_kernel(const float* __restrict__ x,
               const float* __restrict__ W1, const float* __restrict__ b1,
               const float* __restrict__ W2, const float* __restrict__ b2,
               const float* __restrict__ W3, const float* __restrict__ b3,
               const float* __restrict__ W4, const float* __restrict__ b4,
               float* __restrict__ out, int n)
{
    __shared__ float tab[64 * TS];

    // Build the 64-entry mask table (S, sb, E, lb).
    if (threadIdx.x < 64) {
        const int m = threadIdx.x;
        float S00 = 0.f, S01 = 0.f, S10 = 0.f, S11 = 0.f;
        float sb0 = b3[0], sb1 = b3[1];
        float E0 = 0.f, E1 = 0.f, lb = b4[0];
#pragma unroll
        for (int j = 0; j < 6; j++) {
            if ((m >> j) & 1) {
                const float a0 = W1[2 * j], a1 = W1[2 * j + 1], bb = b1[j];
                const float w30 = W3[j], w31 = W3[6 + j], w4j = W4[j];
                S00 = fmaf(w30, a0, S00); S01 = fmaf(w30, a1, S01); sb0 = fmaf(w30, bb, sb0);
                S10 = fmaf(w31, a0, S10); S11 = fmaf(w31, a1, S11); sb1 = fmaf(w31, bb, sb1);
                E0  = fmaf(w4j, a0, E0);  E1  = fmaf(w4j, a1, E1);  lb  = fmaf(w4j, bb, lb);
            }
        }
        float* e = tab + m * TS;
        e[0] = S00; e[1] = S01; e[2] = S10; e[3] = S11;
        e[4] = sb0; e[5] = sb1;
        e[6] = E0;  e[7] = E1;  e[8] = lb;
    }

    // Per-thread weight registers, loaded ONCE, amortized over the grid-stride loop.
    W1p w;
#pragma unroll
    for (int p = 0; p < 3; p++) {
        w.c0[p] = pk2(__ldg(W1 + 4 * p),     __ldg(W1 + 4 * p + 2));
        w.c1[p] = pk2(__ldg(W1 + 4 * p + 1), __ldg(W1 + 4 * p + 3));
        w.bp[p] = pk2(__ldg(b1 + 2 * p),     __ldg(b1 + 2 * p + 1));
    }
    float w2r[12];
#pragma unroll
    for (int j = 0; j < 6; j++) {
        w2r[j]     = __ldg(W2 + j);
        w2r[6 + j] = __ldg(W2 + 6 + j);
    }
    const float gb0 = __ldg(b2 + 0);
    const float gb1 = __ldg(b2 + 1);
    __syncthreads();

    const int np = n >> 1;  // pairs of rows
    const int stride = gridDim.x * blockDim.x;
    int p = blockIdx.x * blockDim.x + threadIdx.x;

    // 3 pairs per loop body: 9 LDG.128 issued before any tail (MLP=9).
    for (; p + 2 * stride < np; p += 3 * stride) {
        const int pb = p + stride;
        const int pc = p + 2 * stride;
        const float4* xa = reinterpret_cast<const float4*>(x + (size_t)p  * 12);
        const float4* xb = reinterpret_cast<const float4*>(x + (size_t)pb * 12);
        const float4* xc = reinterpret_cast<const float4*>(x + (size_t)pc * 12);
        const float4 a0 = xa[0], a1 = xa[1], a2 = xa[2];
        const float4 b0 = xb[0], b1v = xb[1], b2v = xb[2];
        const float4 c0 = xc[0], c1v = xc[1], c2v = xc[2];

        float4 oa, ob, oc;
        do_pair(a0, a1, a2, w, w2r, gb0, gb1, tab, oa);
        reinterpret_cast<float4*>(out)[p] = oa;
        do_pair(b0, b1v, b2v, w, w2r, gb0, gb1, tab, ob);
        reinterpret_cast<float4*>(out)[pb] = ob;
        do_pair(c0, c1v, c2v, w, w2r, gb0, gb1, tab, oc);
        reinterpret_cast<float4*>(out)[pc] = oc;
    }

    // Remainder: up to 2 pairs left for this thread.
    for (; p < np; p += stride) {
        const float4* xa = reinterpret_cast<const float4*>(x + (size_t)p * 12);
        const float4 a0 = xa[0], a1 = xa[1], a2 = xa[2];
        float4 oa;
        do_pair(a0, a1, a2, w, w2r, gb0, gb1, tab, oa);
        reinterpret_cast<float4*>(out)[p] = oa;
    }

    // Tail (n odd) — n is even here; kept for safety.
    if ((n & 1) && blockIdx.x == 0 && threadIdx.x == 0) {
        const int row = n - 1;
        const float* xr = x + (size_t)row * 6;
        float t0, t1;
        compute_row(xr[0], xr[1], xr[2], xr[3], xr[4], xr[5],
                    w, w2r, gb0, gb1, tab, t0, t1);
        out[(size_t)row * 2 + 0] = t0;
        out[(size_t)row * 2 + 1] = t1;
    }
}

extern "C" void kernel_launch(void* const* d_in, const int* in_sizes, int n_in,
                              void* d_out, int out_size)
{
    const float* x  = (const float*)d_in[0];
    const float* W1 = (const float*)d_in[1];
    const float* b1 = (const float*)d_in[2];
    const float* W2 = (const float*)d_in[3];
    const float* b2 = (const float*)d_in[4];
    const float* W3 = (const float*)d_in[5];
    const float* b3 = (const float*)d_in[6];
    const float* W4 = (const float*)d_in[7];
    const float* b4 = (const float*)d_in[8];
    float* out = (float*)d_out;

    const int n = in_sizes[0] / 6;   // rows

    // Persistent-style grid: 5 blocks/SM resident, grid-stride (~3.7 triple-iters/thread)
    const int threads = 128;
    const int blocks = 148 * 5;
    lnn_tau_kernel<<<blocks, threads>>>(x, W1, b1, W2, b2, W3, b3, W4, b4, out, n);
}